// round 1
// baseline (speedup 1.0000x reference)
#include <cuda_runtime.h>

// Problem constants
#define DMODEL 256
#define NHEAD  4
#define HD     64
#define NLAYER 8
#define DFF    1024
#define VOCAB  100
#define LT     256
#define BBATCH 2
#define FHH    32
#define FWW    256
#define SMEMN  (FHH*FWW)      // 8192 memory tokens
#define LB     (LT*BBATCH)    // 512 target rows
#define SBR    (SMEMN*BBATCH) // 16384 memory rows
#define BNH    (BBATCH*NHEAD) // 8 attention batches

#define LN10K 9.210340371976184f

// -------- scratch (device globals, allocation-free) --------
__device__ float g_mem[SBR*DMODEL];       // 16 MB
__device__ float g_ck [SBR*DMODEL];       // 16 MB
__device__ float g_cv [SBR*DMODEL];       // 16 MB
__device__ float g_scores[BNH*LT*SMEMN];  // 64 MB (also reused for self-attn scores)
__device__ float g_tgt[LB*DMODEL];
__device__ float g_q  [LB*DMODEL];
__device__ float g_k  [LB*DMODEL];
__device__ float g_v  [LB*DMODEL];
__device__ float g_ao [LB*DMODEL];
__device__ float g_t2 [LB*DMODEL];
__device__ float g_ffh[LB*DFF];

// -------- memory tensor: features + 2D positional encoding --------
// mem[(s*B+b)*D + c] = features[b,c,h,w] + pe2d(c,h,w), s = h*FW + w
__global__ void mem_kernel(const float* __restrict__ features, float* __restrict__ mem) {
    int idx = blockIdx.x * 256 + threadIdx.x;   // over SBR*DMODEL = 4.19M
    int c   = idx & (DMODEL-1);
    int row = idx >> 8;            // s*B + b
    int b   = row & (BBATCH-1);
    int s   = row >> 1;
    int h   = s / FWW;
    int w   = s % FWW;
    float pe;
    if (c < DMODEL/2) {
        int e = c & ~1;
        float div = __expf(-(float)e / (float)DMODEL * LN10K);
        float arg = (float)h * div;
        pe = (c & 1) ? cosf(arg) : sinf(arg);
    } else {
        int e = (c - DMODEL/2) & ~1;
        float div = __expf(-(float)e / (float)DMODEL * LN10K);
        float arg = (float)w * div;
        pe = (c & 1) ? cosf(arg) : sinf(arg);
    }
    mem[idx] = features[(((size_t)b*DMODEL + c)*FHH + h)*FWW + w] + pe;
}

// -------- token embedding + 1D positional encoding --------
__global__ void embed_kernel(const int* __restrict__ tokens, const float* __restrict__ emb,
                             float* __restrict__ tgt) {
    int idx = blockIdx.x * 256 + threadIdx.x;   // over LB*DMODEL
    int c   = idx & (DMODEL-1);
    int row = idx >> 8;            // l*B + b
    int l   = row >> 1;
    int tok = tokens[row];
    int e = c & ~1;
    float div = __expf(-(float)e / (float)DMODEL * LN10K);
    float arg = (float)l * div;
    float pe = (c & 1) ? cosf(arg) : sinf(arg);
    tgt[idx] = emb[(size_t)tok*DMODEL + c] + pe;
}

// -------- generic tiled SGEMM: C = scale*(A[M,K] * B[N,K]^T + bias), optional relu ----
// Batched via grid.z with element-offset strides aB/bB/cB (head slicing uses stride 64).
__global__ __launch_bounds__(256) void gemm_nt(
    const float* __restrict__ A, int lda, int aB,
    const float* __restrict__ Bm, int ldb, int bB,
    const float* __restrict__ bias,
    float* __restrict__ C, int ldc, int cB,
    int M, int N, int K, float scale, int relu)
{
    __shared__ float As[16][68];
    __shared__ float Bs[16][68];
    A  += (size_t)blockIdx.z * aB;
    Bm += (size_t)blockIdx.z * bB;
    C  += (size_t)blockIdx.z * cB;
    int row0 = blockIdx.y * 64, col0 = blockIdx.x * 64;
    int tid = threadIdx.x;
    int tx = tid & 15, ty = tid >> 4;
    int lc = tid & 15, lr = tid >> 4;
    float acc[4][4] = {};
    for (int k0 = 0; k0 < K; k0 += 16) {
        #pragma unroll
        for (int it = 0; it < 4; it++)
            As[lc][lr + it*16] = A[(size_t)(row0 + lr + it*16) * lda + k0 + lc];
        #pragma unroll
        for (int it = 0; it < 4; it++) {
            int n = col0 + lr + it*16;
            Bs[lc][lr + it*16] = (n < N) ? Bm[(size_t)n * ldb + k0 + lc] : 0.0f;
        }
        __syncthreads();
        #pragma unroll
        for (int kk = 0; kk < 16; kk++) {
            float4 av = *(const float4*)&As[kk][ty*4];
            float4 bv = *(const float4*)&Bs[kk][tx*4];
            acc[0][0] += av.x*bv.x; acc[0][1] += av.x*bv.y; acc[0][2] += av.x*bv.z; acc[0][3] += av.x*bv.w;
            acc[1][0] += av.y*bv.x; acc[1][1] += av.y*bv.y; acc[1][2] += av.y*bv.z; acc[1][3] += av.y*bv.w;
            acc[2][0] += av.z*bv.x; acc[2][1] += av.z*bv.y; acc[2][2] += av.z*bv.z; acc[2][3] += av.z*bv.w;
            acc[3][0] += av.w*bv.x; acc[3][1] += av.w*bv.y; acc[3][2] += av.w*bv.z; acc[3][3] += av.w*bv.w;
        }
        __syncthreads();
    }
    #pragma unroll
    for (int i = 0; i < 4; i++) {
        int m = row0 + ty*4 + i;
        #pragma unroll
        for (int j = 0; j < 4; j++) {
            int n = col0 + tx*4 + j;
            if (n < N) {
                float vv = acc[i][j];
                if (bias) vv += bias[n];
                vv *= scale;
                if (relu) vv = fmaxf(vv, 0.0f);
                C[(size_t)m*ldc + n] = vv;
            }
        }
    }
}

// -------- NN GEMM: C[M,N] = A[M,K] * B[K,N] (used for attn_weights @ V) --------
__global__ __launch_bounds__(256) void gemm_nn(
    const float* __restrict__ A, int lda, int aB,
    const float* __restrict__ Bm, int ldb, int bB,
    float* __restrict__ C, int ldc, int cB,
    int M, int N, int K)
{
    __shared__ float As[16][68];
    __shared__ float Bs[16][68];
    A  += (size_t)blockIdx.z * aB;
    Bm += (size_t)blockIdx.z * bB;
    C  += (size_t)blockIdx.z * cB;
    int row0 = blockIdx.y * 64, col0 = blockIdx.x * 64;
    int tid = threadIdx.x;
    int tx = tid & 15, ty = tid >> 4;
    int lc = tid & 15, lr = tid >> 4;
    float acc[4][4] = {};
    for (int k0 = 0; k0 < K; k0 += 16) {
        #pragma unroll
        for (int it = 0; it < 4; it++)
            As[lc][lr + it*16] = A[(size_t)(row0 + lr + it*16) * lda + k0 + lc];
        #pragma unroll
        for (int it = 0; it < 4; it++) {
            int kk = (tid >> 6) + it*4;
            int n  = tid & 63;
            Bs[kk][n] = Bm[(size_t)(k0 + kk) * ldb + col0 + n];
        }
        __syncthreads();
        #pragma unroll
        for (int kk = 0; kk < 16; kk++) {
            float4 av = *(const float4*)&As[kk][ty*4];
            float4 bv = *(const float4*)&Bs[kk][tx*4];
            acc[0][0] += av.x*bv.x; acc[0][1] += av.x*bv.y; acc[0][2] += av.x*bv.z; acc[0][3] += av.x*bv.w;
            acc[1][0] += av.y*bv.x; acc[1][1] += av.y*bv.y; acc[1][2] += av.y*bv.z; acc[1][3] += av.y*bv.w;
            acc[2][0] += av.z*bv.x; acc[2][1] += av.z*bv.y; acc[2][2] += av.z*bv.z; acc[2][3] += av.z*bv.w;
            acc[3][0] += av.w*bv.x; acc[3][1] += av.w*bv.y; acc[3][2] += av.w*bv.z; acc[3][3] += av.w*bv.w;
        }
        __syncthreads();
    }
    #pragma unroll
    for (int i = 0; i < 4; i++) {
        int m = row0 + ty*4 + i;
        #pragma unroll
        for (int j = 0; j < 4; j++) {
            int n = col0 + tx*4 + j;
            if (n < N)
                C[(size_t)m*ldc + n] = acc[i][j];
        }
    }
}

// -------- row softmax (optionally causal). rows are contiguous (row*Sx). --------
__global__ void softmax_kernel(float* __restrict__ sc, int Sx, int causal) {
    __shared__ float shm[8];
    int row = blockIdx.x;        // n*LT + l
    int l   = row & (LT-1);
    float* p = sc + (size_t)row * Sx;
    int limit = causal ? (l + 1) : Sx;
    int tid = threadIdx.x;

    float mx = -1e30f;
    for (int s = tid; s < limit; s += 256) mx = fmaxf(mx, p[s]);
    for (int o = 16; o; o >>= 1) mx = fmaxf(mx, __shfl_xor_sync(0xffffffffu, mx, o));
    if ((tid & 31) == 0) shm[tid >> 5] = mx;
    __syncthreads();
    if (tid < 32) {
        float t = (tid < 8) ? shm[tid] : -1e30f;
        for (int o = 4; o; o >>= 1) t = fmaxf(t, __shfl_xor_sync(0xffffffffu, t, o));
        if (tid == 0) shm[0] = t;
    }
    __syncthreads();
    mx = shm[0];
    __syncthreads();

    float sum = 0.0f;
    for (int s = tid; s < limit; s += 256) { float e = expf(p[s] - mx); p[s] = e; sum += e; }
    for (int o = 16; o; o >>= 1) sum += __shfl_xor_sync(0xffffffffu, sum, o);
    if ((tid & 31) == 0) shm[tid >> 5] = sum;
    __syncthreads();
    if (tid < 32) {
        float t = (tid < 8) ? shm[tid] : 0.0f;
        for (int o = 4; o; o >>= 1) t += __shfl_xor_sync(0xffffffffu, t, o);
        if (tid == 0) shm[0] = t;
    }
    __syncthreads();
    float inv = 1.0f / shm[0];
    for (int s = tid; s < Sx; s += 256) p[s] = (s < limit) ? p[s] * inv : 0.0f;
}

// -------- fused residual add + LayerNorm (in place on tgt) --------
__global__ void add_ln_kernel(float* __restrict__ tgt, const float* __restrict__ t2,
                              const float* __restrict__ g, const float* __restrict__ b) {
    __shared__ float shm[8];
    int row = blockIdx.x, c = threadIdx.x;   // 256 threads = DMODEL
    size_t idx = (size_t)row * DMODEL + c;
    float x = tgt[idx] + t2[idx];

    float s = x;
    for (int o = 16; o; o >>= 1) s += __shfl_xor_sync(0xffffffffu, s, o);
    if ((c & 31) == 0) shm[c >> 5] = s;
    __syncthreads();
    if (c < 32) {
        float t = (c < 8) ? shm[c] : 0.0f;
        for (int o = 4; o; o >>= 1) t += __shfl_xor_sync(0xffffffffu, t, o);
        if (c == 0) shm[0] = t;
    }
    __syncthreads();
    float mean = shm[0] * (1.0f / DMODEL);
    __syncthreads();

    float d0 = x - mean;
    s = d0 * d0;
    for (int o = 16; o; o >>= 1) s += __shfl_xor_sync(0xffffffffu, s, o);
    if ((c & 31) == 0) shm[c >> 5] = s;
    __syncthreads();
    if (c < 32) {
        float t = (c < 8) ? shm[c] : 0.0f;
        for (int o = 4; o; o >>= 1) t += __shfl_xor_sync(0xffffffffu, t, o);
        if (c == 0) shm[0] = t;
    }
    __syncthreads();
    float var = shm[0] * (1.0f / DMODEL);
    tgt[idx] = d0 * rsqrtf(var + 1e-5f) * g[c] + b[c];
}

extern "C" void kernel_launch(void* const* d_in, const int* in_sizes, int n_in,
                              void* d_out, int out_size) {
    const int*   tokens   = (const int*)  d_in[0];
    const float* features = (const float*)d_in[1];
    const float* emb      = (const float*)d_in[2];
    const float* sa_w     = (const float*)d_in[3];
    const float* sa_b     = (const float*)d_in[4];
    const float* ca_w     = (const float*)d_in[5];
    const float* ca_b     = (const float*)d_in[6];
    const float* ln_g     = (const float*)d_in[7];
    const float* ln_b     = (const float*)d_in[8];
    const float* ff_w1    = (const float*)d_in[9];
    const float* ff_b1    = (const float*)d_in[10];
    const float* ff_w2    = (const float*)d_in[11];
    const float* ff_b2    = (const float*)d_in[12];
    const float* out_w    = (const float*)d_in[13];
    const float* out_b    = (const float*)d_in[14];
    float* out = (float*)d_out;

    float *mem, *ck, *cv, *sc, *tgt, *q, *k, *v, *ao, *t2, *ffh;
    cudaGetSymbolAddress((void**)&mem, g_mem);
    cudaGetSymbolAddress((void**)&ck,  g_ck);
    cudaGetSymbolAddress((void**)&cv,  g_cv);
    cudaGetSymbolAddress((void**)&sc,  g_scores);
    cudaGetSymbolAddress((void**)&tgt, g_tgt);
    cudaGetSymbolAddress((void**)&q,   g_q);
    cudaGetSymbolAddress((void**)&k,   g_k);
    cudaGetSymbolAddress((void**)&v,   g_v);
    cudaGetSymbolAddress((void**)&ao,  g_ao);
    cudaGetSymbolAddress((void**)&t2,  g_t2);
    cudaGetSymbolAddress((void**)&ffh, g_ffh);

    mem_kernel<<<(SBR*DMODEL)/256, 256>>>(features, mem);
    embed_kernel<<<(LB*DMODEL)/256, 256>>>(tokens, emb, tgt);

    const float qscale = 0.125f;   // 1/sqrt(64)
    const int DD = DMODEL*DMODEL;

    for (int i = 0; i < NLAYER; i++) {
        const float* W  = sa_w + (size_t)i*4*DD;
        const float* Bi = sa_b + (size_t)i*4*DMODEL;

        // ---- self-attention ----
        gemm_nt<<<dim3(DMODEL/64, LB/64), 256>>>(tgt, DMODEL,0, W+0*DD, DMODEL,0, Bi+0*DMODEL, q, DMODEL,0, LB,DMODEL,DMODEL, qscale, 0);
        gemm_nt<<<dim3(DMODEL/64, LB/64), 256>>>(tgt, DMODEL,0, W+1*DD, DMODEL,0, Bi+1*DMODEL, k, DMODEL,0, LB,DMODEL,DMODEL, 1.0f, 0);
        gemm_nt<<<dim3(DMODEL/64, LB/64), 256>>>(tgt, DMODEL,0, W+2*DD, DMODEL,0, Bi+2*DMODEL, v, DMODEL,0, LB,DMODEL,DMODEL, 1.0f, 0);
        // scores[n,l,s] = q . k  (per head, head slice stride 64)
        gemm_nt<<<dim3(LT/64, LT/64, BNH), 256>>>(q, BBATCH*DMODEL, HD, k, BBATCH*DMODEL, HD, (const float*)0,
                                                  sc, LT, LT*LT, LT, LT, HD, 1.0f, 0);
        softmax_kernel<<<BNH*LT, 256>>>(sc, LT, 1);
        gemm_nn<<<dim3(1, LT/64, BNH), 256>>>(sc, LT, LT*LT, v, BBATCH*DMODEL, HD,
                                              ao, BBATCH*DMODEL, HD, LT, HD, LT);
        gemm_nt<<<dim3(DMODEL/64, LB/64), 256>>>(ao, DMODEL,0, W+3*DD, DMODEL,0, Bi+3*DMODEL, t2, DMODEL,0, LB,DMODEL,DMODEL, 1.0f, 0);
        add_ln_kernel<<<LB, DMODEL>>>(tgt, t2, ln_g + (size_t)(i*3+0)*DMODEL, ln_b + (size_t)(i*3+0)*DMODEL);

        // ---- cross-attention ----
        const float* Wc = ca_w + (size_t)i*4*DD;
        const float* Bc = ca_b + (size_t)i*4*DMODEL;
        gemm_nt<<<dim3(DMODEL/64, LB/64), 256>>>(tgt, DMODEL,0, Wc+0*DD, DMODEL,0, Bc+0*DMODEL, q, DMODEL,0, LB,DMODEL,DMODEL, qscale, 0);
        gemm_nt<<<dim3(DMODEL/64, SBR/64), 256>>>(mem, DMODEL,0, Wc+1*DD, DMODEL,0, Bc+1*DMODEL, ck, DMODEL,0, SBR,DMODEL,DMODEL, 1.0f, 0);
        gemm_nt<<<dim3(DMODEL/64, SBR/64), 256>>>(mem, DMODEL,0, Wc+2*DD, DMODEL,0, Bc+2*DMODEL, cv, DMODEL,0, SBR,DMODEL,DMODEL, 1.0f, 0);
        gemm_nt<<<dim3(SMEMN/64, LT/64, BNH), 256>>>(q, BBATCH*DMODEL, HD, ck, BBATCH*DMODEL, HD, (const float*)0,
                                                     sc, SMEMN, LT*SMEMN, LT, SMEMN, HD, 1.0f, 0);
        softmax_kernel<<<BNH*LT, 256>>>(sc, SMEMN, 0);
        gemm_nn<<<dim3(1, LT/64, BNH), 256>>>(sc, SMEMN, LT*SMEMN, cv, BBATCH*DMODEL, HD,
                                              ao, BBATCH*DMODEL, HD, LT, HD, SMEMN);
        gemm_nt<<<dim3(DMODEL/64, LB/64), 256>>>(ao, DMODEL,0, Wc+3*DD, DMODEL,0, Bc+3*DMODEL, t2, DMODEL,0, LB,DMODEL,DMODEL, 1.0f, 0);
        add_ln_kernel<<<LB, DMODEL>>>(tgt, t2, ln_g + (size_t)(i*3+1)*DMODEL, ln_b + (size_t)(i*3+1)*DMODEL);

        // ---- FFN ----
        gemm_nt<<<dim3(DFF/64, LB/64), 256>>>(tgt, DMODEL,0, ff_w1 + (size_t)i*DFF*DMODEL, DMODEL,0, ff_b1 + (size_t)i*DFF,
                                              ffh, DFF,0, LB,DFF,DMODEL, 1.0f, 1);
        gemm_nt<<<dim3(DMODEL/64, LB/64), 256>>>(ffh, DFF,0, ff_w2 + (size_t)i*DMODEL*DFF, DFF,0, ff_b2 + (size_t)i*DMODEL,
                                                 t2, DMODEL,0, LB,DMODEL,DFF, 1.0f, 0);
        add_ln_kernel<<<LB, DMODEL>>>(tgt, t2, ln_g + (size_t)(i*3+2)*DMODEL, ln_b + (size_t)(i*3+2)*DMODEL);
    }

    // final vocab projection -> d_out [L,B,V]
    gemm_nt<<<dim3((VOCAB+63)/64, LB/64), 256>>>(tgt, DMODEL,0, out_w, DMODEL,0, out_b,
                                                 out, VOCAB,0, LB,VOCAB,DMODEL, 1.0f, 0);
}

// round 3
// speedup vs baseline: 2.2372x; 2.2372x over previous
#include <cuda_runtime.h>

// Problem constants
#define DMODEL 256
#define NHEAD  4
#define HD     64
#define NLAYER 8
#define DFF    1024
#define VOCAB  100
#define LT     256
#define BBATCH 2
#define FHH    32
#define FWW    256
#define SMEMN  (FHH*FWW)      // 8192 memory tokens
#define LB     (LT*BBATCH)    // 512 target rows
#define SBR    (SMEMN*BBATCH) // 16384 memory rows
#define BNH    (BBATCH*NHEAD) // 8 attention batches

#define LN10K 9.210340371976184f

// -------- scratch (device globals, allocation-free) --------
__device__ float g_mem[SBR*DMODEL];        // 16 MB
__device__ float g_ckv[2*SBR*DMODEL];      // 32 MB (ck, cv)
__device__ float g_scores[BNH*LT*SMEMN];   // 64 MB
__device__ float g_qkv[3*LB*DMODEL];
__device__ float g_tgt[LB*DMODEL];
__device__ float g_ao [LB*DMODEL];
__device__ float g_t2 [LB*DMODEL];
__device__ float g_ffh[LB*DFF];
__device__ float g_part[BNH*16*LT*HD];     // split-K partials

// -------- memory tensor: features + 2D positional encoding --------
__global__ void mem_kernel(const float* __restrict__ features, float* __restrict__ mem) {
    int idx = blockIdx.x * 256 + threadIdx.x;
    int c   = idx & (DMODEL-1);
    int row = idx >> 8;            // s*B + b
    int b   = row & (BBATCH-1);
    int s   = row >> 1;
    int h   = s / FWW;
    int w   = s % FWW;
    float pe;
    if (c < DMODEL/2) {
        int e = c & ~1;
        float div = __expf(-(float)e / (float)DMODEL * LN10K);
        float arg = (float)h * div;
        pe = (c & 1) ? cosf(arg) : sinf(arg);
    } else {
        int e = (c - DMODEL/2) & ~1;
        float div = __expf(-(float)e / (float)DMODEL * LN10K);
        float arg = (float)w * div;
        pe = (c & 1) ? cosf(arg) : sinf(arg);
    }
    mem[idx] = features[(((size_t)b*DMODEL + c)*FHH + h)*FWW + w] + pe;
}

// -------- token embedding + 1D positional encoding --------
__global__ void embed_kernel(const int* __restrict__ tokens, const float* __restrict__ emb,
                             float* __restrict__ tgt) {
    int idx = blockIdx.x * 256 + threadIdx.x;
    int c   = idx & (DMODEL-1);
    int row = idx >> 8;            // l*B + b
    int l   = row >> 1;
    int tok = tokens[row];
    int e = c & ~1;
    float div = __expf(-(float)e / (float)DMODEL * LN10K);
    float arg = (float)l * div;
    float pe = (c & 1) ? cosf(arg) : sinf(arg);
    tgt[idx] = emb[(size_t)tok*DMODEL + c] + pe;
}

// -------- generic tiled SGEMM: C = scale*(A[M,K] * B[N,K]^T + bias), optional relu ----
// Batched via grid.z with element-offset strides aB/bB/biasB/cB.
__global__ __launch_bounds__(256) void gemm_nt(
    const float* __restrict__ A, int lda, int aB,
    const float* __restrict__ Bm, int ldb, int bB,
    const float* __restrict__ bias, int biasB,
    float* __restrict__ C, int ldc, int cB,
    int M, int N, int K, float scale, int relu)
{
    __shared__ float As[16][68];
    __shared__ float Bs[16][68];
    A  += (size_t)blockIdx.z * aB;
    Bm += (size_t)blockIdx.z * bB;
    C  += (size_t)blockIdx.z * cB;
    if (bias) bias += (size_t)blockIdx.z * biasB;
    int row0 = blockIdx.y * 64, col0 = blockIdx.x * 64;
    int tid = threadIdx.x;
    int tx = tid & 15, ty = tid >> 4;
    int lc = tid & 15, lr = tid >> 4;
    float acc[4][4] = {};
    for (int k0 = 0; k0 < K; k0 += 16) {
        #pragma unroll
        for (int it = 0; it < 4; it++)
            As[lc][lr + it*16] = A[(size_t)(row0 + lr + it*16) * lda + k0 + lc];
        #pragma unroll
        for (int it = 0; it < 4; it++) {
            int n = col0 + lr + it*16;
            Bs[lc][lr + it*16] = (n < N) ? Bm[(size_t)n * ldb + k0 + lc] : 0.0f;
        }
        __syncthreads();
        #pragma unroll
        for (int kk = 0; kk < 16; kk++) {
            float4 av = *(const float4*)&As[kk][ty*4];
            float4 bv = *(const float4*)&Bs[kk][tx*4];
            acc[0][0] += av.x*bv.x; acc[0][1] += av.x*bv.y; acc[0][2] += av.x*bv.z; acc[0][3] += av.x*bv.w;
            acc[1][0] += av.y*bv.x; acc[1][1] += av.y*bv.y; acc[1][2] += av.y*bv.z; acc[1][3] += av.y*bv.w;
            acc[2][0] += av.z*bv.x; acc[2][1] += av.z*bv.y; acc[2][2] += av.z*bv.z; acc[2][3] += av.z*bv.w;
            acc[3][0] += av.w*bv.x; acc[3][1] += av.w*bv.y; acc[3][2] += av.w*bv.z; acc[3][3] += av.w*bv.w;
        }
        __syncthreads();
    }
    #pragma unroll
    for (int i = 0; i < 4; i++) {
        int m = row0 + ty*4 + i;
        #pragma unroll
        for (int j = 0; j < 4; j++) {
            int n = col0 + tx*4 + j;
            if (n < N) {
                float vv = acc[i][j];
                if (bias) vv += bias[n];
                vv *= scale;
                if (relu) vv = fmaxf(vv, 0.0f);
                C[(size_t)m*ldc + n] = vv;
            }
        }
    }
}

// -------- split-K NT GEMM: partials P[z][M*N] = A[M,kslice] * B[N,kslice]^T --------
__global__ __launch_bounds__(256) void gemm_nt_sk(
    const float* __restrict__ A, int lda, int aB,
    const float* __restrict__ Bm, int ldb, int bB,
    float* __restrict__ P,
    int M, int N, int K, int ksplit)
{
    __shared__ float As[16][68];
    __shared__ float Bs[16][68];
    int ks = blockIdx.z % ksplit, batch = blockIdx.z / ksplit;
    A  += (size_t)batch * aB;
    Bm += (size_t)batch * bB;
    P  += (size_t)blockIdx.z * M * N;
    int kbeg = ks * (K / ksplit), kend = kbeg + K / ksplit;
    int row0 = blockIdx.y * 64, col0 = blockIdx.x * 64;
    int tid = threadIdx.x;
    int tx = tid & 15, ty = tid >> 4;
    int lc = tid & 15, lr = tid >> 4;
    float acc[4][4] = {};
    for (int k0 = kbeg; k0 < kend; k0 += 16) {
        #pragma unroll
        for (int it = 0; it < 4; it++)
            As[lc][lr + it*16] = A[(size_t)(row0 + lr + it*16) * lda + k0 + lc];
        #pragma unroll
        for (int it = 0; it < 4; it++) {
            int n = col0 + lr + it*16;
            Bs[lc][lr + it*16] = (n < N) ? Bm[(size_t)n * ldb + k0 + lc] : 0.0f;
        }
        __syncthreads();
        #pragma unroll
        for (int kk = 0; kk < 16; kk++) {
            float4 av = *(const float4*)&As[kk][ty*4];
            float4 bv = *(const float4*)&Bs[kk][tx*4];
            acc[0][0] += av.x*bv.x; acc[0][1] += av.x*bv.y; acc[0][2] += av.x*bv.z; acc[0][3] += av.x*bv.w;
            acc[1][0] += av.y*bv.x; acc[1][1] += av.y*bv.y; acc[1][2] += av.y*bv.z; acc[1][3] += av.y*bv.w;
            acc[2][0] += av.z*bv.x; acc[2][1] += av.z*bv.y; acc[2][2] += av.z*bv.z; acc[2][3] += av.z*bv.w;
            acc[3][0] += av.w*bv.x; acc[3][1] += av.w*bv.y; acc[3][2] += av.w*bv.z; acc[3][3] += av.w*bv.w;
        }
        __syncthreads();
    }
    #pragma unroll
    for (int i = 0; i < 4; i++) {
        int m = row0 + ty*4 + i;
        #pragma unroll
        for (int j = 0; j < 4; j++) {
            int n = col0 + tx*4 + j;
            if (n < N) P[(size_t)m*N + n] = acc[i][j];
        }
    }
}

// -------- split-K NN GEMM (attn_weights @ V): partials P[z][M*N] --------
__global__ __launch_bounds__(256) void gemm_nn_sk(
    const float* __restrict__ A, int lda, int aB,
    const float* __restrict__ Bm, int ldb, int bB,
    float* __restrict__ P,
    int M, int N, int K, int ksplit)
{
    __shared__ float As[16][68];
    __shared__ float Bs[16][68];
    int ks = blockIdx.z % ksplit, batch = blockIdx.z / ksplit;
    A  += (size_t)batch * aB;
    Bm += (size_t)batch * bB;
    P  += (size_t)blockIdx.z * M * N;
    int kbeg = ks * (K / ksplit), kend = kbeg + K / ksplit;
    int row0 = blockIdx.y * 64, col0 = blockIdx.x * 64;
    int tid = threadIdx.x;
    int tx = tid & 15, ty = tid >> 4;
    int lc = tid & 15, lr = tid >> 4;
    float acc[4][4] = {};
    for (int k0 = kbeg; k0 < kend; k0 += 16) {
        #pragma unroll
        for (int it = 0; it < 4; it++)
            As[lc][lr + it*16] = A[(size_t)(row0 + lr + it*16) * lda + k0 + lc];
        #pragma unroll
        for (int it = 0; it < 4; it++) {
            int kk = (tid >> 6) + it*4;
            int n  = tid & 63;
            Bs[kk][n] = Bm[(size_t)(k0 + kk) * ldb + col0 + n];
        }
        __syncthreads();
        #pragma unroll
        for (int kk = 0; kk < 16; kk++) {
            float4 av = *(const float4*)&As[kk][ty*4];
            float4 bv = *(const float4*)&Bs[kk][tx*4];
            acc[0][0] += av.x*bv.x; acc[0][1] += av.x*bv.y; acc[0][2] += av.x*bv.z; acc[0][3] += av.x*bv.w;
            acc[1][0] += av.y*bv.x; acc[1][1] += av.y*bv.y; acc[1][2] += av.y*bv.z; acc[1][3] += av.y*bv.w;
            acc[2][0] += av.z*bv.x; acc[2][1] += av.z*bv.y; acc[2][2] += av.z*bv.z; acc[2][3] += av.z*bv.w;
            acc[3][0] += av.w*bv.x; acc[3][1] += av.w*bv.y; acc[3][2] += av.w*bv.z; acc[3][3] += av.w*bv.w;
        }
        __syncthreads();
    }
    #pragma unroll
    for (int i = 0; i < 4; i++) {
        int m = row0 + ty*4 + i;
        #pragma unroll
        for (int j = 0; j < 4; j++) {
            int n = col0 + tx*4 + j;
            if (n < N) P[(size_t)m*N + n] = acc[i][j];
        }
    }
}

// -------- split-K reduce: C[batch*cB + m*ldc + n] = relu(sum_ks P + bias) --------
__global__ void reduce_sk(const float* __restrict__ P, float* __restrict__ C,
                          int ldc, int cB, int M, int N, int ksplit,
                          const float* __restrict__ bias, int relu)
{
    int idx = blockIdx.x * 256 + threadIdx.x;   // over nbatch*M*N (exact multiple)
    int n = idx % N;
    int mb = idx / N;
    int m = mb % M;
    int batch = mb / M;
    const float* p = P + ((size_t)batch*ksplit)*M*N + (size_t)m*N + n;
    float s = 0.0f;
    for (int ksi = 0; ksi < ksplit; ksi++) s += p[(size_t)ksi*M*N];
    if (bias) s += bias[n];
    if (relu) s = fmaxf(s, 0.0f);
    C[(size_t)batch*cB + (size_t)m*ldc + n] = s;
}

// -------- row softmax (optionally causal) --------
__global__ void softmax_kernel(float* __restrict__ sc, int Sx, int causal) {
    __shared__ float shm[8];
    int row = blockIdx.x;        // n*LT + l
    int l   = row & (LT-1);
    float* p = sc + (size_t)row * Sx;
    int limit = causal ? (l + 1) : Sx;
    int tid = threadIdx.x;

    float mx = -1e30f;
    for (int s = tid; s < limit; s += 256) mx = fmaxf(mx, p[s]);
    for (int o = 16; o; o >>= 1) mx = fmaxf(mx, __shfl_xor_sync(0xffffffffu, mx, o));
    if ((tid & 31) == 0) shm[tid >> 5] = mx;
    __syncthreads();
    if (tid < 32) {
        float t = (tid < 8) ? shm[tid] : -1e30f;
        for (int o = 4; o; o >>= 1) t = fmaxf(t, __shfl_xor_sync(0xffffffffu, t, o));
        if (tid == 0) shm[0] = t;
    }
    __syncthreads();
    mx = shm[0];
    __syncthreads();

    float sum = 0.0f;
    for (int s = tid; s < limit; s += 256) { float e = expf(p[s] - mx); p[s] = e; sum += e; }
    for (int o = 16; o; o >>= 1) sum += __shfl_xor_sync(0xffffffffu, sum, o);
    if ((tid & 31) == 0) shm[tid >> 5] = sum;
    __syncthreads();
    if (tid < 32) {
        float t = (tid < 8) ? shm[tid] : 0.0f;
        for (int o = 4; o; o >>= 1) t += __shfl_xor_sync(0xffffffffu, t, o);
        if (tid == 0) shm[0] = t;
    }
    __syncthreads();
    float inv = 1.0f / shm[0];
    for (int s = tid; s < Sx; s += 256) p[s] = (s < limit) ? p[s] * inv : 0.0f;
}

// -------- fused residual add + LayerNorm (in place on tgt) --------
__global__ void add_ln_kernel(float* __restrict__ tgt, const float* __restrict__ t2,
                              const float* __restrict__ g, const float* __restrict__ b) {
    __shared__ float shm[8];
    int row = blockIdx.x, c = threadIdx.x;
    size_t idx = (size_t)row * DMODEL + c;
    float x = tgt[idx] + t2[idx];

    float s = x;
    for (int o = 16; o; o >>= 1) s += __shfl_xor_sync(0xffffffffu, s, o);
    if ((c & 31) == 0) shm[c >> 5] = s;
    __syncthreads();
    if (c < 32) {
        float t = (c < 8) ? shm[c] : 0.0f;
        for (int o = 4; o; o >>= 1) t += __shfl_xor_sync(0xffffffffu, t, o);
        if (c == 0) shm[0] = t;
    }
    __syncthreads();
    float mean = shm[0] * (1.0f / DMODEL);
    __syncthreads();

    float d0 = x - mean;
    s = d0 * d0;
    for (int o = 16; o; o >>= 1) s += __shfl_xor_sync(0xffffffffu, s, o);
    if ((c & 31) == 0) shm[c >> 5] = s;
    __syncthreads();
    if (c < 32) {
        float t = (c < 8) ? shm[c] : 0.0f;
        for (int o = 4; o; o >>= 1) t += __shfl_xor_sync(0xffffffffu, t, o);
        if (c == 0) shm[0] = t;
    }
    __syncthreads();
    float var = shm[0] * (1.0f / DMODEL);
    tgt[idx] = d0 * rsqrtf(var + 1e-5f) * g[c] + b[c];
}

extern "C" void kernel_launch(void* const* d_in, const int* in_sizes, int n_in,
                              void* d_out, int out_size) {
    const int*   tokens   = (const int*)  d_in[0];
    const float* features = (const float*)d_in[1];
    const float* emb      = (const float*)d_in[2];
    const float* sa_w     = (const float*)d_in[3];
    const float* sa_b     = (const float*)d_in[4];
    const float* ca_w     = (const float*)d_in[5];
    const float* ca_b     = (const float*)d_in[6];
    const float* ln_g     = (const float*)d_in[7];
    const float* ln_b     = (const float*)d_in[8];
    const float* ff_w1    = (const float*)d_in[9];
    const float* ff_b1    = (const float*)d_in[10];
    const float* ff_w2    = (const float*)d_in[11];
    const float* ff_b2    = (const float*)d_in[12];
    const float* out_w    = (const float*)d_in[13];
    const float* out_b    = (const float*)d_in[14];
    float* out = (float*)d_out;

    float *mem, *ckv, *sc, *qkv, *tgt, *ao, *t2, *ffh, *part;
    cudaGetSymbolAddress((void**)&mem, g_mem);
    cudaGetSymbolAddress((void**)&ckv, g_ckv);
    cudaGetSymbolAddress((void**)&sc,  g_scores);
    cudaGetSymbolAddress((void**)&qkv, g_qkv);
    cudaGetSymbolAddress((void**)&tgt, g_tgt);
    cudaGetSymbolAddress((void**)&ao,  g_ao);
    cudaGetSymbolAddress((void**)&t2,  g_t2);
    cudaGetSymbolAddress((void**)&ffh, g_ffh);
    cudaGetSymbolAddress((void**)&part,g_part);

    float* q = qkv;
    float* k = qkv + (size_t)LB*DMODEL;
    float* v = qkv + (size_t)2*LB*DMODEL;
    float* ck = ckv;
    float* cv = ckv + (size_t)SBR*DMODEL;

    mem_kernel<<<(SBR*DMODEL)/256, 256>>>(features, mem);
    embed_kernel<<<(LB*DMODEL)/256, 256>>>(tokens, emb, tgt);

    const float qscale = 0.125f;   // 1/sqrt(64)
    const int DD = DMODEL*DMODEL;

    for (int i = 0; i < NLAYER; i++) {
        const float* W  = sa_w + (size_t)i*4*DD;
        const float* Bi = sa_b + (size_t)i*4*DMODEL;

        // ---- self-attention ----
        // fused q,k,v projections (grid.z = 3)
        gemm_nt<<<dim3(DMODEL/64, LB/64, 3), 256>>>(tgt, DMODEL,0, W, DMODEL,DD, Bi,DMODEL,
                                                    qkv, DMODEL, LB*DMODEL, LB,DMODEL,DMODEL, 1.0f, 0);
        // scores[n,l,s] = qscale * (q . k)
        gemm_nt<<<dim3(LT/64, LT/64, BNH), 256>>>(q, BBATCH*DMODEL, HD, k, BBATCH*DMODEL, HD, (const float*)0,0,
                                                  sc, LT, LT*LT, LT, LT, HD, qscale, 0);
        softmax_kernel<<<BNH*LT, 256>>>(sc, LT, 1);
        // attn @ V, split-K 4
        gemm_nn_sk<<<dim3(1, LT/64, BNH*4), 256>>>(sc, LT, LT*LT, v, BBATCH*DMODEL, HD,
                                                   part, LT, HD, LT, 4);
        reduce_sk<<<(BNH*LT*HD)/256, 256>>>(part, ao, BBATCH*DMODEL, HD, LT, HD, 4, (const float*)0, 0);
        gemm_nt<<<dim3(DMODEL/64, LB/64), 256>>>(ao, DMODEL,0, W+3*DD, DMODEL,0, Bi+3*DMODEL,0,
                                                 t2, DMODEL,0, LB,DMODEL,DMODEL, 1.0f, 0);
        add_ln_kernel<<<LB, DMODEL>>>(tgt, t2, ln_g + (size_t)(i*3+0)*DMODEL, ln_b + (size_t)(i*3+0)*DMODEL);

        // ---- cross-attention ----
        const float* Wc = ca_w + (size_t)i*4*DD;
        const float* Bc = ca_b + (size_t)i*4*DMODEL;
        gemm_nt<<<dim3(DMODEL/64, LB/64), 256>>>(tgt, DMODEL,0, Wc, DMODEL,0, Bc,0,
                                                 q, DMODEL,0, LB,DMODEL,DMODEL, 1.0f, 0);
        // fused k,v projections of memory (grid.z = 2)
        gemm_nt<<<dim3(DMODEL/64, SBR/64, 2), 256>>>(mem, DMODEL,0, Wc+DD, DMODEL,DD, Bc+DMODEL,DMODEL,
                                                     ckv, DMODEL, SBR*DMODEL, SBR,DMODEL,DMODEL, 1.0f, 0);
        gemm_nt<<<dim3(SMEMN/64, LT/64, BNH), 256>>>(q, BBATCH*DMODEL, HD, ck, BBATCH*DMODEL, HD, (const float*)0,0,
                                                     sc, SMEMN, LT*SMEMN, LT, SMEMN, HD, qscale, 0);
        softmax_kernel<<<BNH*LT, 256>>>(sc, SMEMN, 0);
        // attn @ V, split-K 16 over K=8192
        gemm_nn_sk<<<dim3(1, LT/64, BNH*16), 256>>>(sc, SMEMN, LT*SMEMN, cv, BBATCH*DMODEL, HD,
                                                    part, LT, HD, SMEMN, 16);
        reduce_sk<<<(BNH*LT*HD)/256, 256>>>(part, ao, BBATCH*DMODEL, HD, LT, HD, 16, (const float*)0, 0);
        gemm_nt<<<dim3(DMODEL/64, LB/64), 256>>>(ao, DMODEL,0, Wc+3*DD, DMODEL,0, Bc+3*DMODEL,0,
                                                 t2, DMODEL,0, LB,DMODEL,DMODEL, 1.0f, 0);
        add_ln_kernel<<<LB, DMODEL>>>(tgt, t2, ln_g + (size_t)(i*3+1)*DMODEL, ln_b + (size_t)(i*3+1)*DMODEL);

        // ---- FFN ----
        gemm_nt<<<dim3(DFF/64, LB/64), 256>>>(tgt, DMODEL,0, ff_w1 + (size_t)i*DFF*DMODEL, DMODEL,0, ff_b1 + (size_t)i*DFF,0,
                                              ffh, DFF,0, LB,DFF,DMODEL, 1.0f, 1);
        // FFN2 split-K 4 over K=1024
        gemm_nt_sk<<<dim3(DMODEL/64, LB/64, 4), 256>>>(ffh, DFF,0, ff_w2 + (size_t)i*DMODEL*DFF, DFF,0,
                                                       part, LB, DMODEL, DFF, 4);
        reduce_sk<<<(LB*DMODEL)/256, 256>>>(part, t2, DMODEL, 0, LB, DMODEL, 4,
                                            ff_b2 + (size_t)i*DMODEL, 0);
        add_ln_kernel<<<LB, DMODEL>>>(tgt, t2, ln_g + (size_t)(i*3+2)*DMODEL, ln_b + (size_t)(i*3+2)*DMODEL);
    }

    // final vocab projection -> d_out [L,B,V]
    gemm_nt<<<dim3((VOCAB+63)/64, LB/64), 256>>>(tgt, DMODEL,0, out_w, DMODEL,0, out_b,0,
                                                 out, VOCAB,0, LB,VOCAB,DMODEL, 1.0f, 0);
}